// round 1
// baseline (speedup 1.0000x reference)
#include <cuda_runtime.h>
#include <math.h>

#define Q 256      // B*P = 4*64
#define D 768
#define NKEYS 2048
#define RADJ 12
#define TOPK 16

// ---------------- scratch (static device memory; no allocations) ----------------
__device__ float g_keys[NKEYS * D];          // normalized keys        6.3 MB
__device__ float g_adjsum[NKEYS * NKEYS];    // sum over r of adjacency 16.8 MB
__device__ float g_scores[Q * NKEYS];        // 2.1 MB
__device__ float g_w[Q * TOPK];
__device__ int   g_idx[Q * TOPK];
__device__ float g_nei[Q * NKEYS];           // 2.1 MB
__device__ float g_opart[4 * Q * D];         // split-K partials 3.1 MB

// ---------------- 1) normalize keys rows ----------------
__global__ __launch_bounds__(256) void knorm_kernel(const float* __restrict__ kp) {
    int row = blockIdx.x;
    const float* src = kp + row * D;
    float* dst = g_keys + row * D;
    float s = 0.f;
    for (int i = threadIdx.x; i < D; i += 256) { float v = src[i]; s += v * v; }
    __shared__ float red[8];
    #pragma unroll
    for (int o = 16; o > 0; o >>= 1) s += __shfl_xor_sync(0xffffffffu, s, o);
    if ((threadIdx.x & 31) == 0) red[threadIdx.x >> 5] = s;
    __syncthreads();
    if (threadIdx.x == 0) {
        float t = 0.f;
        #pragma unroll
        for (int i = 0; i < 8; i++) t += red[i];
        red[0] = rsqrtf(t + 1e-12f);
    }
    __syncthreads();
    float inv = red[0];
    for (int i = threadIdx.x; i < D; i += 256) dst[i] = src[i] * inv;
}

// ---------------- 2) adjacency sum over r ----------------
__global__ __launch_bounds__(256) void adjsum_kernel(const float* __restrict__ adj) {
    const int i = blockIdx.x * 256 + threadIdx.x;       // float4 index, N*N/4 total
    const float4* a = (const float4*)adj;
    const int stride = (NKEYS * NKEYS) / 4;
    float4 acc = a[i];
    #pragma unroll
    for (int r = 1; r < RADJ; r++) {
        float4 v = a[i + r * stride];
        acc.x += v.x; acc.y += v.y; acc.z += v.z; acc.w += v.w;
    }
    ((float4*)g_adjsum)[i] = acc;
}

// ---------------- 3) scores GEMM (NT): C[q][n] = sum_d pos[q][d]*keys[n][d] ----------------
#define GBM 64
#define GBN 64
#define GBK 32
#define GPAD 68
__global__ __launch_bounds__(256) void scores_gemm(const float* __restrict__ A) {
    const int n0 = blockIdx.x * GBN;
    const int m0 = blockIdx.y * GBM;
    __shared__ float As[GBK][GPAD];   // [k][m]
    __shared__ float Bs[GBK][GPAD];   // [k][n]
    const int tid = threadIdx.x;
    const int tx = tid & 15, ty = tid >> 4;
    float acc[4][4] = {};
    for (int kt = 0; kt < D; kt += GBK) {
        #pragma unroll
        for (int l = 0; l < 2; l++) {
            int f = tid + l * 256;          // 0..511, 8 float4 per row
            int row = f >> 3;
            int c4 = f & 7;
            float4 v = *(const float4*)(A + (m0 + row) * D + kt + c4 * 4);
            As[c4*4+0][row] = v.x; As[c4*4+1][row] = v.y;
            As[c4*4+2][row] = v.z; As[c4*4+3][row] = v.w;
            float4 u = *(const float4*)(g_keys + (n0 + row) * D + kt + c4 * 4);
            Bs[c4*4+0][row] = u.x; Bs[c4*4+1][row] = u.y;
            Bs[c4*4+2][row] = u.z; Bs[c4*4+3][row] = u.w;
        }
        __syncthreads();
        #pragma unroll
        for (int kk = 0; kk < GBK; kk++) {
            float a[4], b[4];
            #pragma unroll
            for (int i = 0; i < 4; i++) a[i] = As[kk][ty * 4 + i];
            #pragma unroll
            for (int j = 0; j < 4; j++) b[j] = Bs[kk][tx * 4 + j];
            #pragma unroll
            for (int i = 0; i < 4; i++)
                #pragma unroll
                for (int j = 0; j < 4; j++) acc[i][j] += a[i] * b[j];
        }
        __syncthreads();
    }
    #pragma unroll
    for (int i = 0; i < 4; i++) {
        float4 v = make_float4(acc[i][0], acc[i][1], acc[i][2], acc[i][3]);
        *(float4*)(g_scores + (m0 + ty * 4 + i) * NKEYS + n0 + tx * 4) = v;
    }
}

// ---------------- 4) top-k + softmax per query ----------------
__global__ __launch_bounds__(256) void topk_kernel() {
    const int q = blockIdx.x;
    __shared__ float sv[NKEYS];
    __shared__ float rv[8];
    __shared__ int   ri[8];
    __shared__ float svals[TOPK];
    __shared__ int   sidx[TOPK];
    const int tid = threadIdx.x;
    for (int i = tid; i < NKEYS; i += 256) sv[i] = g_scores[q * NKEYS + i];
    __syncthreads();
    for (int t = 0; t < TOPK; t++) {
        float best = -1e30f; int bi = 0;
        for (int i = tid; i < NKEYS; i += 256) {
            float v = sv[i];
            if (v > best) { best = v; bi = i; }
        }
        #pragma unroll
        for (int o = 16; o > 0; o >>= 1) {
            float ov = __shfl_xor_sync(0xffffffffu, best, o);
            int   oi = __shfl_xor_sync(0xffffffffu, bi, o);
            if (ov > best || (ov == best && oi < bi)) { best = ov; bi = oi; }
        }
        if ((tid & 31) == 0) { rv[tid >> 5] = best; ri[tid >> 5] = bi; }
        __syncthreads();
        if (tid == 0) {
            float bb = rv[0]; int bbi = ri[0];
            #pragma unroll
            for (int wgi = 1; wgi < 8; wgi++) {
                if (rv[wgi] > bb || (rv[wgi] == bb && ri[wgi] < bbi)) { bb = rv[wgi]; bbi = ri[wgi]; }
            }
            svals[t] = bb; sidx[t] = bbi;
            sv[bbi] = -1e30f;
        }
        __syncthreads();
    }
    if (tid == 0) {
        float m = svals[0];          // found in descending order
        float e[TOPK], sum = 0.f;
        #pragma unroll
        for (int t = 0; t < TOPK; t++) { e[t] = expf(svals[t] - m); sum += e[t]; }
        float invs = 1.f / sum;
        #pragma unroll
        for (int t = 0; t < TOPK; t++) {
            g_w[q * TOPK + t] = e[t] * invs;
            g_idx[q * TOPK + t] = sidx[t];
        }
    }
}

// ---------------- 5) nei[q][n] = sum_k w[q][k] * adj_sum[idx[q][k]][n] ----------------
__global__ __launch_bounds__(256) void nei_kernel() {
    const int q = blockIdx.x;
    __shared__ float w[TOPK];
    __shared__ int   id[TOPK];
    const int tid = threadIdx.x;
    if (tid < TOPK) { w[tid] = g_w[q * TOPK + tid]; id[tid] = g_idx[q * TOPK + tid]; }
    __syncthreads();
    #pragma unroll
    for (int l = 0; l < 2; l++) {
        int p = tid + l * 256;               // float4 col index, 512 per row
        float4 acc = make_float4(0.f, 0.f, 0.f, 0.f);
        #pragma unroll
        for (int t = 0; t < TOPK; t++) {
            const float4 v = ((const float4*)(g_adjsum + (size_t)id[t] * NKEYS))[p];
            float wt = w[t];
            acc.x += wt * v.x; acc.y += wt * v.y; acc.z += wt * v.z; acc.w += wt * v.w;
        }
        ((float4*)(g_nei + q * NKEYS))[p] = acc;
    }
}

// ---------------- 6) out GEMM (NN, split-K=4): part[z][q][d] = sum_n nei[q][n]*keys[n][d] ----------------
__global__ __launch_bounds__(256) void out_gemm() {
    const int d0 = blockIdx.x * GBN;     // 12 tiles over D=768
    const int q0 = blockIdx.y * GBM;     // 4 tiles over Q=256
    const int z  = blockIdx.z;           // split-K of 4, 512 each
    const int kbase = z * (NKEYS / 4);
    __shared__ float As[GBK][GPAD];      // [k][q]
    __shared__ float Bs[GBK][GPAD];      // [k][d]
    const int tid = threadIdx.x;
    const int tx = tid & 15, ty = tid >> 4;
    float acc[4][4] = {};
    for (int kt = kbase; kt < kbase + NKEYS / 4; kt += GBK) {
        #pragma unroll
        for (int l = 0; l < 2; l++) {
            int f = tid + l * 256;
            // A tile: 64 q-rows x 32 k-cols (transpose into As)
            int arow = f >> 3, ac4 = f & 7;
            float4 v = *(const float4*)(g_nei + (q0 + arow) * NKEYS + kt + ac4 * 4);
            As[ac4*4+0][arow] = v.x; As[ac4*4+1][arow] = v.y;
            As[ac4*4+2][arow] = v.z; As[ac4*4+3][arow] = v.w;
            // B tile: 32 k-rows x 64 d-cols (direct)
            int brow = f >> 4, bc4 = f & 15;
            float4 u = *(const float4*)(g_keys + (kt + brow) * D + d0 + bc4 * 4);
            *(float4*)&Bs[brow][bc4 * 4] = u;
        }
        __syncthreads();
        #pragma unroll
        for (int kk = 0; kk < GBK; kk++) {
            float a[4], b[4];
            #pragma unroll
            for (int i = 0; i < 4; i++) a[i] = As[kk][ty * 4 + i];
            #pragma unroll
            for (int j = 0; j < 4; j++) b[j] = Bs[kk][tx * 4 + j];
            #pragma unroll
            for (int i = 0; i < 4; i++)
                #pragma unroll
                for (int j = 0; j < 4; j++) acc[i][j] += a[i] * b[j];
        }
        __syncthreads();
    }
    #pragma unroll
    for (int i = 0; i < 4; i++) {
        float4 v = make_float4(acc[i][0], acc[i][1], acc[i][2], acc[i][3]);
        *(float4*)(g_opart + ((size_t)z * Q + q0 + ty * 4 + i) * D + d0 + tx * 4) = v;
    }
}

// ---------------- 7) reduce split-K partials ----------------
__global__ __launch_bounds__(256) void reduce_kernel(float* __restrict__ out) {
    const int i = blockIdx.x * 256 + threadIdx.x;   // float4 index over Q*D/4
    const float4* p = (const float4*)g_opart;
    const int stride = (Q * D) / 4;
    float4 a = p[i];
    #pragma unroll
    for (int z = 1; z < 4; z++) {
        float4 v = p[i + z * stride];
        a.x += v.x; a.y += v.y; a.z += v.z; a.w += v.w;
    }
    ((float4*)out)[i] = a;
}

extern "C" void kernel_launch(void* const* d_in, const int* in_sizes, int n_in,
                              void* d_out, int out_size) {
    const float* positions = (const float*)d_in[0];   // (4,64,768)
    const float* keys_p    = (const float*)d_in[1];   // (2048,768)
    const float* adjacency = (const float*)d_in[2];   // (12,2048,2048)
    float* out = (float*)d_out;                       // (4,64,768)

    knorm_kernel<<<NKEYS, 256>>>(keys_p);
    adjsum_kernel<<<(NKEYS * NKEYS / 4) / 256, 256>>>(adjacency);
    scores_gemm<<<dim3(NKEYS / GBN, Q / GBM), 256>>>(positions);
    topk_kernel<<<Q, 256>>>();
    nei_kernel<<<Q, 256>>>();
    out_gemm<<<dim3(D / GBN, Q / GBM, 4), 256>>>();
    reduce_kernel<<<(Q * D / 4) / 256, 256>>>(out);
}

// round 2
// speedup vs baseline: 1.0914x; 1.0914x over previous
#include <cuda_runtime.h>
#include <math.h>

#define Q 256      // B*P = 4*64
#define D 768
#define NKEYS 2048
#define RADJ 12
#define TOPK 16

// ---------------- scratch (static device memory; no allocations) ----------------
__device__ float g_keys[NKEYS * D];          // normalized keys        6.3 MB
__device__ float g_adjsum[NKEYS * NKEYS];    // sum over r of adjacency 16.8 MB
__device__ float g_scores[Q * NKEYS];        // 2.1 MB
__device__ float g_w[Q * TOPK];
__device__ int   g_idx[Q * TOPK];
__device__ float g_nei[Q * NKEYS];           // 2.1 MB
__device__ float g_opart[4 * Q * D];         // split-K partials 3.1 MB

// ---------------- 1) normalize keys rows ----------------
__global__ __launch_bounds__(256) void knorm_kernel(const float* __restrict__ kp) {
    int row = blockIdx.x;
    const float* src = kp + row * D;
    float* dst = g_keys + row * D;
    float s = 0.f;
    for (int i = threadIdx.x; i < D; i += 256) { float v = src[i]; s += v * v; }
    __shared__ float red[8];
    #pragma unroll
    for (int o = 16; o > 0; o >>= 1) s += __shfl_xor_sync(0xffffffffu, s, o);
    if ((threadIdx.x & 31) == 0) red[threadIdx.x >> 5] = s;
    __syncthreads();
    if (threadIdx.x == 0) {
        float t = 0.f;
        #pragma unroll
        for (int i = 0; i < 8; i++) t += red[i];
        red[0] = rsqrtf(t + 1e-12f);
    }
    __syncthreads();
    float inv = red[0];
    for (int i = threadIdx.x; i < D; i += 256) dst[i] = src[i] * inv;
}

// ---------------- 2+3 FUSED: scores GEMM (blocks 0..127) + adjacency r-sum (blocks 128..4223)
// Scores blocks are scheduled first (wave 1) and run long on the FMA pipe while
// adjsum blocks stream 201MB from HBM concurrently -> overlap compute & memory.
#define GBM 64
#define GBN 64
#define GBK 32
#define GPAD 68
#define NSCOREBLK 128
__global__ __launch_bounds__(256) void fused_scores_adjsum(const float* __restrict__ A,
                                                           const float* __restrict__ adj) {
    __shared__ float As[GBK][GPAD];   // [k][m]
    __shared__ float Bs[GBK][GPAD];   // [k][n]
    const int tid = threadIdx.x;

    if (blockIdx.x >= NSCOREBLK) {
        // ----- adjacency sum over r -----
        const int i = (blockIdx.x - NSCOREBLK) * 256 + tid;   // float4 index
        const float4* a = (const float4*)adj;
        const int stride = (NKEYS * NKEYS) / 4;
        float4 acc = a[i];
        #pragma unroll
        for (int r = 1; r < RADJ; r++) {
            float4 v = a[i + r * stride];
            acc.x += v.x; acc.y += v.y; acc.z += v.z; acc.w += v.w;
        }
        ((float4*)g_adjsum)[i] = acc;
        return;
    }

    // ----- scores GEMM (NT): C[q][n] = sum_d pos[q][d]*keys[n][d] -----
    const int n0 = (blockIdx.x & 31) * GBN;
    const int m0 = (blockIdx.x >> 5) * GBM;
    const int tx = tid & 15, ty = tid >> 4;
    float acc[4][4] = {};
    for (int kt = 0; kt < D; kt += GBK) {
        #pragma unroll
        for (int l = 0; l < 2; l++) {
            int f = tid + l * 256;          // 0..511, 8 float4 per row
            int row = f >> 3;
            int c4 = f & 7;
            float4 v = *(const float4*)(A + (m0 + row) * D + kt + c4 * 4);
            As[c4*4+0][row] = v.x; As[c4*4+1][row] = v.y;
            As[c4*4+2][row] = v.z; As[c4*4+3][row] = v.w;
            float4 u = *(const float4*)(g_keys + (n0 + row) * D + kt + c4 * 4);
            Bs[c4*4+0][row] = u.x; Bs[c4*4+1][row] = u.y;
            Bs[c4*4+2][row] = u.z; Bs[c4*4+3][row] = u.w;
        }
        __syncthreads();
        #pragma unroll
        for (int kk = 0; kk < GBK; kk++) {
            float a[4], b[4];
            #pragma unroll
            for (int i = 0; i < 4; i++) a[i] = As[kk][ty * 4 + i];
            #pragma unroll
            for (int j = 0; j < 4; j++) b[j] = Bs[kk][tx * 4 + j];
            #pragma unroll
            for (int i = 0; i < 4; i++)
                #pragma unroll
                for (int j = 0; j < 4; j++) acc[i][j] += a[i] * b[j];
        }
        __syncthreads();
    }
    #pragma unroll
    for (int i = 0; i < 4; i++) {
        float4 v = make_float4(acc[i][0], acc[i][1], acc[i][2], acc[i][3]);
        *(float4*)(g_scores + (m0 + ty * 4 + i) * NKEYS + n0 + tx * 4) = v;
    }
}

// ---------------- 4) top-k + softmax: one WARP per query, no block syncs ----------------
// 2 warps per block, 128 blocks. Scores row staged in smem; 16 rounds of
// warp-argmax (lower-index tie-break matches lax.top_k).
__global__ __launch_bounds__(64) void topk_warp_kernel() {
    __shared__ float sv[2][NKEYS];
    const int wid = threadIdx.x >> 5;
    const int lane = threadIdx.x & 31;
    const int q = blockIdx.x * 2 + wid;
    float* row = sv[wid];
    const float* src = g_scores + q * NKEYS;
    #pragma unroll
    for (int j = 0; j < NKEYS / 32 / 4; j++) {       // 16 float4 per lane
        float4 v = ((const float4*)src)[j * 32 + lane];
        *(float4*)&row[(j * 32 + lane) * 4] = v;
    }
    __syncwarp();

    float bestv[TOPK];
    int   besti[TOPK];
    #pragma unroll 1
    for (int t = 0; t < TOPK; t++) {
        float best = -1e30f; int bi = 0;
        #pragma unroll
        for (int j = 0; j < NKEYS / 32; j++) {
            int i = j * 32 + lane;
            float v = row[i];
            if (v > best) { best = v; bi = i; }
        }
        #pragma unroll
        for (int o = 16; o > 0; o >>= 1) {
            float ov = __shfl_xor_sync(0xffffffffu, best, o);
            int   oi = __shfl_xor_sync(0xffffffffu, bi, o);
            if (ov > best || (ov == best && oi < bi)) { best = ov; bi = oi; }
        }
        bestv[t] = best; besti[t] = bi;
        if ((bi & 31) == lane) row[bi] = -1e30f;     // owning lane eliminates
        __syncwarp();
    }

    if (lane == 0) {
        float m = bestv[0];                          // descending order
        float e[TOPK], sum = 0.f;
        #pragma unroll
        for (int t = 0; t < TOPK; t++) { e[t] = expf(bestv[t] - m); sum += e[t]; }
        float invs = 1.f / sum;
        #pragma unroll
        for (int t = 0; t < TOPK; t++) {
            g_w[q * TOPK + t] = e[t] * invs;
            g_idx[q * TOPK + t] = besti[t];
        }
    }
}

// ---------------- 5) nei[q][n] = sum_k w[q][k] * adj_sum[idx[q][k]][n] ----------------
__global__ __launch_bounds__(256) void nei_kernel() {
    const int q = blockIdx.x;
    __shared__ float w[TOPK];
    __shared__ int   id[TOPK];
    const int tid = threadIdx.x;
    if (tid < TOPK) { w[tid] = g_w[q * TOPK + tid]; id[tid] = g_idx[q * TOPK + tid]; }
    __syncthreads();
    #pragma unroll
    for (int l = 0; l < 2; l++) {
        int p = tid + l * 256;               // float4 col index, 512 per row
        float4 acc = make_float4(0.f, 0.f, 0.f, 0.f);
        #pragma unroll
        for (int t = 0; t < TOPK; t++) {
            const float4 v = ((const float4*)(g_adjsum + (size_t)id[t] * NKEYS))[p];
            float wt = w[t];
            acc.x += wt * v.x; acc.y += wt * v.y; acc.z += wt * v.z; acc.w += wt * v.w;
        }
        ((float4*)(g_nei + q * NKEYS))[p] = acc;
    }
}

// ---------------- 6) out GEMM (NN, split-K=4): part[z][q][d] = sum_n nei[q][n]*keys[n][d] ----------------
__global__ __launch_bounds__(256) void out_gemm() {
    const int d0 = blockIdx.x * GBN;     // 12 tiles over D=768
    const int q0 = blockIdx.y * GBM;     // 4 tiles over Q=256
    const int z  = blockIdx.z;           // split-K of 4, 512 each
    const int kbase = z * (NKEYS / 4);
    __shared__ float As[GBK][GPAD];      // [k][q]
    __shared__ float Bs[GBK][GPAD];      // [k][d]
    const int tid = threadIdx.x;
    const int tx = tid & 15, ty = tid >> 4;
    float acc[4][4] = {};
    for (int kt = kbase; kt < kbase + NKEYS / 4; kt += GBK) {
        #pragma unroll
        for (int l = 0; l < 2; l++) {
            int f = tid + l * 256;
            int arow = f >> 3, ac4 = f & 7;
            float4 v = *(const float4*)(g_nei + (q0 + arow) * NKEYS + kt + ac4 * 4);
            As[ac4*4+0][arow] = v.x; As[ac4*4+1][arow] = v.y;
            As[ac4*4+2][arow] = v.z; As[ac4*4+3][arow] = v.w;
            int brow = f >> 4, bc4 = f & 15;
            float4 u = *(const float4*)(g_keys + (kt + brow) * D + d0 + bc4 * 4);
            *(float4*)&Bs[brow][bc4 * 4] = u;
        }
        __syncthreads();
        #pragma unroll
        for (int kk = 0; kk < GBK; kk++) {
            float a[4], b[4];
            #pragma unroll
            for (int i = 0; i < 4; i++) a[i] = As[kk][ty * 4 + i];
            #pragma unroll
            for (int j = 0; j < 4; j++) b[j] = Bs[kk][tx * 4 + j];
            #pragma unroll
            for (int i = 0; i < 4; i++)
                #pragma unroll
                for (int j = 0; j < 4; j++) acc[i][j] += a[i] * b[j];
        }
        __syncthreads();
    }
    #pragma unroll
    for (int i = 0; i < 4; i++) {
        float4 v = make_float4(acc[i][0], acc[i][1], acc[i][2], acc[i][3]);
        *(float4*)(g_opart + ((size_t)z * Q + q0 + ty * 4 + i) * D + d0 + tx * 4) = v;
    }
}

// ---------------- 7) reduce split-K partials ----------------
__global__ __launch_bounds__(256) void reduce_kernel(float* __restrict__ out) {
    const int i = blockIdx.x * 256 + threadIdx.x;   // float4 index over Q*D/4
    const float4* p = (const float4*)g_opart;
    const int stride = (Q * D) / 4;
    float4 a = p[i];
    #pragma unroll
    for (int z = 1; z < 4; z++) {
        float4 v = p[i + z * stride];
        a.x += v.x; a.y += v.y; a.z += v.z; a.w += v.w;
    }
    ((float4*)out)[i] = a;
}

extern "C" void kernel_launch(void* const* d_in, const int* in_sizes, int n_in,
                              void* d_out, int out_size) {
    const float* positions = (const float*)d_in[0];   // (4,64,768)
    const float* keys_p    = (const float*)d_in[1];   // (2048,768)
    const float* adjacency = (const float*)d_in[2];   // (12,2048,2048)
    float* out = (float*)d_out;                       // (4,64,768)

    knorm_kernel<<<NKEYS, 256>>>(keys_p);
    fused_scores_adjsum<<<NSCOREBLK + (NKEYS * NKEYS / 4) / 256, 256>>>(positions, adjacency);
    topk_warp_kernel<<<Q / 2, 64>>>();
    nei_kernel<<<Q, 256>>>();
    out_gemm<<<dim3(D / GBN, Q / GBM, 4), 256>>>();
    reduce_kernel<<<(Q * D / 4) / 256, 256>>>(out);
}

// round 3
// speedup vs baseline: 1.1092x; 1.0163x over previous
#include <cuda_runtime.h>
#include <math.h>

#define Q 256      // B*P = 4*64
#define D 768
#define NKEYS 2048
#define RADJ 12
#define TOPK 16

// ---------------- scratch (static device memory; no allocations) ----------------
__device__ float g_invn[NKEYS];              // 1/||key_row||
__device__ float g_adjsum[NKEYS * NKEYS];    // sum over r of adjacency 16.8 MB
__device__ float g_scores[Q * NKEYS];        // 2.1 MB
__device__ float g_nei[Q * NKEYS];           // 2.1 MB
__device__ float g_opart[4 * Q * D];         // split-K partials 3.1 MB

// ---------------- 1) key row inverse norms ----------------
__global__ __launch_bounds__(256) void norm_kernel(const float* __restrict__ kp) {
    int row = blockIdx.x;
    const float* src = kp + row * D;
    float s = 0.f;
    for (int i = threadIdx.x; i < D; i += 256) { float v = src[i]; s += v * v; }
    __shared__ float red[8];
    #pragma unroll
    for (int o = 16; o > 0; o >>= 1) s += __shfl_xor_sync(0xffffffffu, s, o);
    if ((threadIdx.x & 31) == 0) red[threadIdx.x >> 5] = s;
    __syncthreads();
    if (threadIdx.x == 0) {
        float t = 0.f;
        #pragma unroll
        for (int i = 0; i < 8; i++) t += red[i];
        g_invn[row] = rsqrtf(t + 1e-12f);
    }
}

// ---------------- 2+3 FUSED: scores GEMM (blocks 0..127) + adjacency r-sum ----------------
#define GBM 64
#define GBN 64
#define GBK 32
#define GPAD 68
#define NSCOREBLK 128
__global__ __launch_bounds__(256) void fused_scores_adjsum(const float* __restrict__ A,
                                                           const float* __restrict__ kp,
                                                           const float* __restrict__ adj) {
    __shared__ float As[GBK][GPAD];   // [k][m]
    __shared__ float Bs[GBK][GPAD];   // [k][n]
    const int tid = threadIdx.x;

    if (blockIdx.x >= NSCOREBLK) {
        // ----- adjacency sum over r -----
        const int i = (blockIdx.x - NSCOREBLK) * 256 + tid;   // float4 index
        const float4* a = (const float4*)adj;
        const int stride = (NKEYS * NKEYS) / 4;
        float4 acc = a[i];
        #pragma unroll
        for (int r = 1; r < RADJ; r++) {
            float4 v = a[i + r * stride];
            acc.x += v.x; acc.y += v.y; acc.z += v.z; acc.w += v.w;
        }
        ((float4*)g_adjsum)[i] = acc;
        return;
    }

    // ----- scores GEMM (NT): C[q][n] = sum_d pos[q][d]*(kp[n][d]*invn[n]) -----
    const int n0 = (blockIdx.x & 31) * GBN;
    const int m0 = (blockIdx.x >> 5) * GBM;
    const int tx = tid & 15, ty = tid >> 4;
    float acc[4][4] = {};
    for (int kt = 0; kt < D; kt += GBK) {
        #pragma unroll
        for (int l = 0; l < 2; l++) {
            int f = tid + l * 256;          // 0..511, 8 float4 per row
            int row = f >> 3;
            int c4 = f & 7;
            float4 v = *(const float4*)(A + (m0 + row) * D + kt + c4 * 4);
            As[c4*4+0][row] = v.x; As[c4*4+1][row] = v.y;
            As[c4*4+2][row] = v.z; As[c4*4+3][row] = v.w;
            float inv = g_invn[n0 + row];
            float4 u = *(const float4*)(kp + (n0 + row) * D + kt + c4 * 4);
            Bs[c4*4+0][row] = u.x * inv; Bs[c4*4+1][row] = u.y * inv;
            Bs[c4*4+2][row] = u.z * inv; Bs[c4*4+3][row] = u.w * inv;
        }
        __syncthreads();
        #pragma unroll
        for (int kk = 0; kk < GBK; kk++) {
            float a[4], b[4];
            #pragma unroll
            for (int i = 0; i < 4; i++) a[i] = As[kk][ty * 4 + i];
            #pragma unroll
            for (int j = 0; j < 4; j++) b[j] = Bs[kk][tx * 4 + j];
            #pragma unroll
            for (int i = 0; i < 4; i++)
                #pragma unroll
                for (int j = 0; j < 4; j++) acc[i][j] += a[i] * b[j];
        }
        __syncthreads();
    }
    #pragma unroll
    for (int i = 0; i < 4; i++) {
        float4 v = make_float4(acc[i][0], acc[i][1], acc[i][2], acc[i][3]);
        *(float4*)(g_scores + (m0 + ty * 4 + i) * NKEYS + n0 + tx * 4) = v;
    }
}

// ---------------- 4+5 FUSED: top-k + softmax + gather, block per query ----------------
__global__ __launch_bounds__(256) void topk_nei_kernel() {
    const int q = blockIdx.x;
    __shared__ float sv[NKEYS];
    __shared__ float sw[TOPK];
    __shared__ int   sid[TOPK];
    const int tid = threadIdx.x;
    const int lane = tid & 31;

    // stage scores row
    #pragma unroll
    for (int j = 0; j < NKEYS / 256 / 4; j++) {   // 2 float4 per thread
        float4 v = ((const float4*)(g_scores + q * NKEYS))[j * 256 + tid];
        *(float4*)&sv[(j * 256 + tid) * 4] = v;
    }
    __syncthreads();

    // warp 0: 16 rounds of argmax (lower-index tie-break), then softmax
    if (tid < 32) {
        float bestv[TOPK]; int besti[TOPK];
        #pragma unroll 1
        for (int t = 0; t < TOPK; t++) {
            float best = -1e30f; int bi = 0;
            #pragma unroll
            for (int j = 0; j < NKEYS / 32; j++) {
                int i = j * 32 + lane;
                float v = sv[i];
                if (v > best) { best = v; bi = i; }
            }
            #pragma unroll
            for (int o = 16; o > 0; o >>= 1) {
                float ov = __shfl_xor_sync(0xffffffffu, best, o);
                int   oi = __shfl_xor_sync(0xffffffffu, bi, o);
                if (ov > best || (ov == best && oi < bi)) { best = ov; bi = oi; }
            }
            bestv[t] = best; besti[t] = bi;
            if ((bi & 31) == lane) sv[bi] = -1e30f;
            __syncwarp();
        }
        if (lane == 0) {
            float m = bestv[0];
            float e[TOPK], sum = 0.f;
            #pragma unroll
            for (int t = 0; t < TOPK; t++) { e[t] = expf(bestv[t] - m); sum += e[t]; }
            float invs = 1.f / sum;
            #pragma unroll
            for (int t = 0; t < TOPK; t++) { sw[t] = e[t] * invs; sid[t] = besti[t]; }
        }
    }
    __syncthreads();

    // all 8 warps: nei[q][n] = sum_t w[t] * adjsum[id[t]][n]
    float w[TOPK]; int id[TOPK];
    #pragma unroll
    for (int t = 0; t < TOPK; t++) { w[t] = sw[t]; id[t] = sid[t]; }
    #pragma unroll
    for (int l = 0; l < 2; l++) {
        int p = tid + l * 256;               // float4 col index, 512 per row
        float4 acc = make_float4(0.f, 0.f, 0.f, 0.f);
        #pragma unroll
        for (int t = 0; t < TOPK; t++) {
            const float4 v = ((const float4*)(g_adjsum + (size_t)id[t] * NKEYS))[p];
            float wt = w[t];
            acc.x += wt * v.x; acc.y += wt * v.y; acc.z += wt * v.z; acc.w += wt * v.w;
        }
        ((float4*)(g_nei + q * NKEYS))[p] = acc;
    }
}

// ---------------- 6) out GEMM (NN, split-K=4): part[z][q][d] = sum_n nei[q][n]*keys[n][d] ----------------
__global__ __launch_bounds__(256) void out_gemm(const float* __restrict__ kp) {
    const int d0 = blockIdx.x * GBN;     // 12 tiles over D=768
    const int q0 = blockIdx.y * GBM;     // 4 tiles over Q=256
    const int z  = blockIdx.z;           // split-K of 4, 512 each
    const int kbase = z * (NKEYS / 4);
    __shared__ float As[GBK][GPAD];      // [k][q]
    __shared__ float Bs[GBK][GPAD];      // [k][d]
    const int tid = threadIdx.x;
    const int tx = tid & 15, ty = tid >> 4;
    float acc[4][4] = {};
    for (int kt = kbase; kt < kbase + NKEYS / 4; kt += GBK) {
        #pragma unroll
        for (int l = 0; l < 2; l++) {
            int f = tid + l * 256;
            int arow = f >> 3, ac4 = f & 7;
            float4 v = *(const float4*)(g_nei + (q0 + arow) * NKEYS + kt + ac4 * 4);
            As[ac4*4+0][arow] = v.x; As[ac4*4+1][arow] = v.y;
            As[ac4*4+2][arow] = v.z; As[ac4*4+3][arow] = v.w;
            int brow = f >> 4, bc4 = f & 15;
            float inv = g_invn[kt + brow];
            float4 u = *(const float4*)(kp + (kt + brow) * D + d0 + bc4 * 4);
            u.x *= inv; u.y *= inv; u.z *= inv; u.w *= inv;
            *(float4*)&Bs[brow][bc4 * 4] = u;
        }
        __syncthreads();
        #pragma unroll
        for (int kk = 0; kk < GBK; kk++) {
            float a[4], b[4];
            #pragma unroll
            for (int i = 0; i < 4; i++) a[i] = As[kk][ty * 4 + i];
            #pragma unroll
            for (int j = 0; j < 4; j++) b[j] = Bs[kk][tx * 4 + j];
            #pragma unroll
            for (int i = 0; i < 4; i++)
                #pragma unroll
                for (int j = 0; j < 4; j++) acc[i][j] += a[i] * b[j];
        }
        __syncthreads();
    }
    #pragma unroll
    for (int i = 0; i < 4; i++) {
        float4 v = make_float4(acc[i][0], acc[i][1], acc[i][2], acc[i][3]);
        *(float4*)(g_opart + ((size_t)z * Q + q0 + ty * 4 + i) * D + d0 + tx * 4) = v;
    }
}

// ---------------- 7) reduce split-K partials ----------------
__global__ __launch_bounds__(256) void reduce_kernel(float* __restrict__ out) {
    const int i = blockIdx.x * 256 + threadIdx.x;   // float4 index over Q*D/4
    const float4* p = (const float4*)g_opart;
    const int stride = (Q * D) / 4;
    float4 a = p[i];
    #pragma unroll
    for (int z = 1; z < 4; z++) {
        float4 v = p[i + z * stride];
        a.x += v.x; a.y += v.y; a.z += v.z; a.w += v.w;
    }
    ((float4*)out)[i] = a;
}

extern "C" void kernel_launch(void* const* d_in, const int* in_sizes, int n_in,
                              void* d_out, int out_size) {
    const float* positions = (const float*)d_in[0];   // (4,64,768)
    const float* keys_p    = (const float*)d_in[1];   // (2048,768)
    const float* adjacency = (const float*)d_in[2];   // (12,2048,2048)
    float* out = (float*)d_out;                       // (4,64,768)

    norm_kernel<<<NKEYS, 256>>>(keys_p);
    fused_scores_adjsum<<<NSCOREBLK + (NKEYS * NKEYS / 4) / 256, 256>>>(positions, keys_p, adjacency);
    topk_nei_kernel<<<Q, 256>>>();
    out_gemm<<<dim3(D / GBN, Q / GBM, 4), 256>>>(keys_p);
    reduce_kernel<<<(Q * D / 4) / 256, 256>>>(out);
}

// round 5
// speedup vs baseline: 1.1550x; 1.0413x over previous
#include <cuda_runtime.h>
#include <math.h>

#define Q 256      // B*P = 4*64
#define D 768
#define NKEYS 2048
#define RADJ 12
#define TOPK 16
#define SPLITK 16

// ---------------- scratch (static device memory; no allocations) ----------------
__device__ float g_invn[NKEYS];              // 1/||key_row||
__device__ float g_adjsum[NKEYS * NKEYS];    // sum over r of adjacency 16.8 MB
__device__ float g_scores[Q * NKEYS];        // 2.1 MB
__device__ float g_nei[Q * NKEYS];           // 2.1 MB
__device__ float g_opart[SPLITK * Q * D];    // split-K partials 12.6 MB

// packed f32x2 FMA: c += a*b on two lanes in one instruction
__device__ __forceinline__ void ffma2(unsigned long long& c, unsigned long long a, unsigned long long b) {
    asm("fma.rn.f32x2 %0, %1, %2, %0;" : "+l"(c) : "l"(a), "l"(b));
}
__device__ __forceinline__ unsigned long long pack_dup(float a) {
    unsigned long long r;
    asm("mov.b64 %0, {%1, %1};" : "=l"(r) : "r"(__float_as_uint(a)));
    return r;
}

// ---------------- 1) key row inverse norms ----------------
__global__ __launch_bounds__(256) void norm_kernel(const float* __restrict__ kp) {
    int row = blockIdx.x;
    const float* src = kp + row * D;
    float s = 0.f;
    for (int i = threadIdx.x; i < D; i += 256) { float v = src[i]; s += v * v; }
    __shared__ float red[8];
    #pragma unroll
    for (int o = 16; o > 0; o >>= 1) s += __shfl_xor_sync(0xffffffffu, s, o);
    if ((threadIdx.x & 31) == 0) red[threadIdx.x >> 5] = s;
    __syncthreads();
    if (threadIdx.x == 0) {
        float t = 0.f;
        #pragma unroll
        for (int i = 0; i < 8; i++) t += red[i];
        g_invn[row] = rsqrtf(t + 1e-12f);
    }
}

// ---------------- 2+3 FUSED: scores GEMM (blocks 0..127) + adjacency r-sum ----------------
#define GBM 64
#define GBN 64
#define GBK 32
#define GPAD 68
#define NSCOREBLK 128
__global__ __launch_bounds__(256) void fused_scores_adjsum(const float* __restrict__ A,
                                                           const float* __restrict__ kp,
                                                           const float* __restrict__ adj) {
    __shared__ float As[GBK][GPAD];   // [k][m]
    __shared__ float Bs[GBK][GPAD];   // [k][n]
    const int tid = threadIdx.x;

    if (blockIdx.x >= NSCOREBLK) {
        // ----- adjacency sum over r -----
        const int i = (blockIdx.x - NSCOREBLK) * 256 + tid;   // float4 index
        const float4* a = (const float4*)adj;
        const int stride = (NKEYS * NKEYS) / 4;
        float4 acc = a[i];
        #pragma unroll
        for (int r = 1; r < RADJ; r++) {
            float4 v = a[i + r * stride];
            acc.x += v.x; acc.y += v.y; acc.z += v.z; acc.w += v.w;
        }
        ((float4*)g_adjsum)[i] = acc;
        return;
    }

    // ----- scores GEMM (NT): C[q][n] = sum_d pos[q][d]*(kp[n][d]*invn[n]) -----
    const int n0 = (blockIdx.x & 31) * GBN;
    const int m0 = (blockIdx.x >> 5) * GBM;
    const int tx = tid & 15, ty = tid >> 4;
    unsigned long long acc2[4][2] = {};
    for (int kt = 0; kt < D; kt += GBK) {
        #pragma unroll
        for (int l = 0; l < 2; l++) {
            int f = tid + l * 256;          // 0..511, 8 float4 per row
            int row = f >> 3;
            int c4 = f & 7;
            float4 v = *(const float4*)(A + (m0 + row) * D + kt + c4 * 4);
            As[c4*4+0][row] = v.x; As[c4*4+1][row] = v.y;
            As[c4*4+2][row] = v.z; As[c4*4+3][row] = v.w;
            float inv = g_invn[n0 + row];
            float4 u = *(const float4*)(kp + (n0 + row) * D + kt + c4 * 4);
            Bs[c4*4+0][row] = u.x * inv; Bs[c4*4+1][row] = u.y * inv;
            Bs[c4*4+2][row] = u.z * inv; Bs[c4*4+3][row] = u.w * inv;
        }
        __syncthreads();
        #pragma unroll
        for (int kk = 0; kk < GBK; kk++) {
            float4 a4 = *(const float4*)&As[kk][ty * 4];
            float4 b4 = *(const float4*)&Bs[kk][tx * 4];
            unsigned long long bp0 = ((const unsigned long long*)&b4)[0];
            unsigned long long bp1 = ((const unsigned long long*)&b4)[1];
            float av[4] = {a4.x, a4.y, a4.z, a4.w};
            #pragma unroll
            for (int i = 0; i < 4; i++) {
                unsigned long long ap = pack_dup(av[i]);
                ffma2(acc2[i][0], ap, bp0);
                ffma2(acc2[i][1], ap, bp1);
            }
        }
        __syncthreads();
    }
    #pragma unroll
    for (int i = 0; i < 4; i++) {
        float4 v;
        *(unsigned long long*)&v.x = acc2[i][0];
        *(unsigned long long*)&v.z = acc2[i][1];
        *(float4*)(g_scores + (m0 + ty * 4 + i) * NKEYS + n0 + tx * 4) = v;
    }
}

// ---------------- 4+5 FUSED: top-k + softmax + gather, block per query ----------------
__global__ __launch_bounds__(256) void topk_nei_kernel() {
    const int q = blockIdx.x;
    __shared__ float sv[NKEYS];
    __shared__ float sw[TOPK];
    __shared__ int   sid[TOPK];
    const int tid = threadIdx.x;
    const int lane = tid & 31;

    #pragma unroll
    for (int j = 0; j < NKEYS / 256 / 4; j++) {   // 2 float4 per thread
        float4 v = ((const float4*)(g_scores + q * NKEYS))[j * 256 + tid];
        *(float4*)&sv[(j * 256 + tid) * 4] = v;
    }
    __syncthreads();

    if (tid < 32) {
        float bestv[TOPK]; int besti[TOPK];
        #pragma unroll 1
        for (int t = 0; t < TOPK; t++) {
            float best = -1e30f; int bi = 0;
            #pragma unroll
            for (int j = 0; j < NKEYS / 32; j++) {
                int i = j * 32 + lane;
                float v = sv[i];
                if (v > best) { best = v; bi = i; }
            }
            #pragma unroll
            for (int o = 16; o > 0; o >>= 1) {
                float ov = __shfl_xor_sync(0xffffffffu, best, o);
                int   oi = __shfl_xor_sync(0xffffffffu, bi, o);
                if (ov > best || (ov == best && oi < bi)) { best = ov; bi = oi; }
            }
            bestv[t] = best; besti[t] = bi;
            if ((bi & 31) == lane) sv[bi] = -1e30f;
            __syncwarp();
        }
        if (lane == 0) {
            float m = bestv[0];
            float e[TOPK], sum = 0.f;
            #pragma unroll
            for (int t = 0; t < TOPK; t++) { e[t] = expf(bestv[t] - m); sum += e[t]; }
            float invs = 1.f / sum;
            #pragma unroll
            for (int t = 0; t < TOPK; t++) { sw[t] = e[t] * invs; sid[t] = besti[t]; }
        }
    }
    __syncthreads();

    float w[TOPK]; int id[TOPK];
    #pragma unroll
    for (int t = 0; t < TOPK; t++) { w[t] = sw[t]; id[t] = sid[t]; }
    #pragma unroll
    for (int l = 0; l < 2; l++) {
        int p = tid + l * 256;               // float4 col index, 512 per row
        float4 acc = make_float4(0.f, 0.f, 0.f, 0.f);
        #pragma unroll
        for (int t = 0; t < TOPK; t++) {
            const float4 v = ((const float4*)(g_adjsum + (size_t)id[t] * NKEYS))[p];
            float wt = w[t];
            acc.x += wt * v.x; acc.y += wt * v.y; acc.z += wt * v.z; acc.w += wt * v.w;
        }
        ((float4*)(g_nei + q * NKEYS))[p] = acc;
    }
}

// ---------------- 6) out GEMM (NN, split-K=16): part[z][q][d] = sum_n nei[q][n]*keys[n][d] ----------------
__global__ __launch_bounds__(256) void out_gemm(const float* __restrict__ kp) {
    const int d0 = blockIdx.x * GBN;     // 12 tiles over D=768
    const int q0 = blockIdx.y * GBM;     // 4 tiles over Q=256
    const int z  = blockIdx.z;           // split-K of 16, 128 each
    const int kbase = z * (NKEYS / SPLITK);
    __shared__ float As[GBK][GPAD];      // [k][q]
    __shared__ float Bs[GBK][GPAD];      // [k][d]
    const int tid = threadIdx.x;
    const int tx = tid & 15, ty = tid >> 4;
    unsigned long long acc2[4][2] = {};
    for (int kt = kbase; kt < kbase + NKEYS / SPLITK; kt += GBK) {
        #pragma unroll
        for (int l = 0; l < 2; l++) {
            int f = tid + l * 256;
            int arow = f >> 3, ac4 = f & 7;
            float4 v = *(const float4*)(g_nei + (q0 + arow) * NKEYS + kt + ac4 * 4);
            As[ac4*4+0][arow] = v.x; As[ac4*4+1][arow] = v.y;
            As[ac4*4+2][arow] = v.z; As[ac4*4+3][arow] = v.w;
            int brow = f >> 4, bc4 = f & 15;
            float inv = g_invn[kt + brow];
            float4 u = *(const float4*)(kp + (kt + brow) * D + d0 + bc4 * 4);
            u.x *= inv; u.y *= inv; u.z *= inv; u.w *= inv;
            *(float4*)&Bs[brow][bc4 * 4] = u;
        }
        __syncthreads();
        #pragma unroll
        for (int kk = 0; kk < GBK; kk++) {
            float4 a4 = *(const float4*)&As[kk][ty * 4];
            float4 b4 = *(const float4*)&Bs[kk][tx * 4];
            unsigned long long bp0 = ((const unsigned long long*)&b4)[0];
            unsigned long long bp1 = ((const unsigned long long*)&b4)[1];
            float av[4] = {a4.x, a4.y, a4.z, a4.w};
            #pragma unroll
            for (int i = 0; i < 4; i++) {
                unsigned long long ap = pack_dup(av[i]);
                ffma2(acc2[i][0], ap, bp0);
                ffma2(acc2[i][1], ap, bp1);
            }
        }
        __syncthreads();
    }
    #pragma unroll
    for (int i = 0; i < 4; i++) {
        float4 v;
        *(unsigned long long*)&v.x = acc2[i][0];
        *(unsigned long long*)&v.z = acc2[i][1];
        *(float4*)(g_opart + ((size_t)z * Q + q0 + ty * 4 + i) * D + d0 + tx * 4) = v;
    }
}

// ---------------- 7) reduce split-K partials ----------------
__global__ __launch_bounds__(256) void reduce_kernel(float* __restrict__ out) {
    const int i = blockIdx.x * 256 + threadIdx.x;   // float4 index over Q*D/4
    const float4* p = (const float4*)g_opart;
    const int stride = (Q * D) / 4;
    float4 a = p[i];
    #pragma unroll
    for (int z = 1; z < SPLITK; z++) {
        float4 v = p[i + z * stride];
        a.x += v.x; a.y += v.y; a.z += v.z; a.w += v.w;
    }
    ((float4*)out)[i] = a;
}

extern "C" void kernel_launch(void* const* d_in, const int* in_sizes, int n_in,
                              void* d_out, int out_size) {
    const float* positions = (const float*)d_in[0];   // (4,64,768)
    const float* keys_p    = (const float*)d_in[1];   // (2048,768)
    const float* adjacency = (const float*)d_in[2];   // (12,2048,2048)
    float* out = (float*)d_out;                       // (4,64,768)

    norm_kernel<<<NKEYS, 256>>>(keys_p);
    fused_scores_adjsum<<<NSCOREBLK + (NKEYS * NKEYS / 4) / 256, 256>>>(positions, keys_p, adjacency);
    topk_nei_kernel<<<Q, 256>>>();
    out_gemm<<<dim3(D / GBN, Q / GBM, SPLITK), 256>>>(keys_p);
    reduce_kernel<<<(Q * D / 4) / 256, 256>>>(out);
}